// round 10
// baseline (speedup 1.0000x reference)
#include <cuda_runtime.h>
#include <cstdint>

// DETRMatcher: reference's softmax/cdist/argmin are dead code w.r.t. outputs
// (scatter of 0 into an all-zero tensor = zeros). Output = 8.1M float32:
//   [0, 1.62M)      : 0.0f           (two int32 zero index tensors)
//   [1.62M, 4.86M)  : outputs_coord  (bitwise copy)
//   [4.86M, 8.10M)  : target_boxes   (bitwise copy)
//
// R9 (flat strided float4, 512 TPB) = best: ncu 10.02us / wall 10.34us.
// R10: sm_100+ 256-bit global ld/st (v8.f32) — 32B per thread, half the
// instructions per byte. All segment boundaries are 32B-divisible.

static constexpr int N32    = 1012500;   // total 32B units (8.1M f32 / 8)
static constexpr int Z32    = 202500;    // zero segment in 32B units
static constexpr int M32    = 607500;    // zeros + coord (Z32 + 405000)
// coord/boxes each: 405000 units

static constexpr int TPB = 512;

__device__ __forceinline__ void ld256(const float* __restrict__ p, float* v)
{
    asm volatile("ld.global.nc.v8.f32 {%0,%1,%2,%3,%4,%5,%6,%7}, [%8];"
                 : "=f"(v[0]), "=f"(v[1]), "=f"(v[2]), "=f"(v[3]),
                   "=f"(v[4]), "=f"(v[5]), "=f"(v[6]), "=f"(v[7])
                 : "l"(p));
}

__device__ __forceinline__ void st256(float* __restrict__ p, const float* v)
{
    asm volatile("st.global.v8.f32 [%0], {%1,%2,%3,%4,%5,%6,%7,%8};"
                 :: "l"(p),
                    "f"(v[0]), "f"(v[1]), "f"(v[2]), "f"(v[3]),
                    "f"(v[4]), "f"(v[5]), "f"(v[6]), "f"(v[7])
                 : "memory");
}

__global__ void __launch_bounds__(TPB)
detr_matcher_pack_v8(const float* __restrict__ coord,
                     const float* __restrict__ boxes,
                     float* __restrict__ out)
{
    const int j = blockIdx.x * TPB + threadIdx.x;   // 32B-unit index
    if (j >= N32) return;

    float v[8];
    if (j >= M32) {                       // boxes copy (40%)
        ld256(boxes + 8 * (j - M32), v);
    } else if (j >= Z32) {                // coord copy (40%)
        ld256(coord + 8 * (j - Z32), v);
    } else {                              // zero segment (20%)
#pragma unroll
        for (int k = 0; k < 8; k++) v[k] = 0.f;
    }
    st256(out + 8 * j, v);
}

extern "C" void kernel_launch(void* const* d_in, const int* in_sizes, int n_in,
                              void* d_out, int out_size)
{
    // metadata order: outputs_class, outputs_coord, target_classes, target_boxes
    const float* coord = (const float*)d_in[1];
    const float* boxes = (const float*)d_in[3];
    float* out = (float*)d_out;

    const int blocks = (N32 + TPB - 1) / TPB;   // 1978
    detr_matcher_pack_v8<<<blocks, TPB>>>(coord, boxes, out);
}

// round 11
// speedup vs baseline: 1.0209x; 1.0209x over previous
#include <cuda_runtime.h>

// DETRMatcher — FINAL.
//
// The reference's softmax/cdist/argmin machinery is dead code w.r.t. the
// returned tensors: matched_indices and tgt_idx scatter 0 into all-zero
// arrays (=> zeros), out_bbox/tgt_bbox are bitwise copies. With JAX x64
// disabled the output concatenation promotes to float32 (8.1M elements):
//   [0, 1.62M)      : 0.0f           (two int32 zero index tensors)
//   [1.62M, 4.86M)  : outputs_coord  (bitwise copy, 3.24M f32)
//   [4.86M, 8.10M)  : target_boxes   (bitwise copy, 3.24M f32)
//
// Optimization history (ncu kernel time):
//   R2  flat strided float4, 256TPB          10.18us
//   R3  MLP4 front-batched                   10.37us
//   R4  memset+memcpy graph nodes            ~23us   (regression)
//   R5  one-wave contiguous chunks           10.72us
//   R6  segment-specialized + __ldcs/__stcg  11.46us
//   R9  flat strided float4, 512TPB          10.02us  <- best (wall 10.34us)
//   R10 256-bit v8.f32                       10.02us  (identical; issue 10.8%)
// Six independent levers all neutral at ~5.8 TB/s combined L2 throughput:
// the 58.3MB of irreducible traffic + graph-replay ramp IS the floor.

static constexpr int V_ZERO  = 405000;                 // float4 slots of zeros
static constexpr int V_COORD = 810000;                 // float4 slots per copy
static constexpr int V_TOTAL = V_ZERO + 2 * V_COORD;   // 2,025,000
static constexpr int V_MID   = V_ZERO + V_COORD;       // 1,215,000

static constexpr int TPB = 512;

__global__ void __launch_bounds__(TPB)
detr_matcher_pack_f32(const float4* __restrict__ coord,
                      const float4* __restrict__ boxes,
                      float4* __restrict__ out)
{
    const int j = blockIdx.x * TPB + threadIdx.x;
    if (j >= V_TOTAL) return;

    float4 v;
    if (j >= V_MID) {                    // boxes copy (40% of elements)
        v = boxes[j - V_MID];
    } else if (j >= V_ZERO) {            // coord copy (40%)
        v = coord[j - V_ZERO];
    } else {                             // zero segment (20%)
        v = make_float4(0.f, 0.f, 0.f, 0.f);
    }
    out[j] = v;
}

extern "C" void kernel_launch(void* const* d_in, const int* in_sizes, int n_in,
                              void* d_out, int out_size)
{
    // metadata order: outputs_class, outputs_coord, target_classes, target_boxes
    const float4* coord = (const float4*)d_in[1];
    const float4* boxes = (const float4*)d_in[3];
    float4* out = (float4*)d_out;

    const int blocks = (V_TOTAL + TPB - 1) / TPB;   // 3956
    detr_matcher_pack_f32<<<blocks, TPB>>>(coord, boxes, out);
}